// round 8
// baseline (speedup 1.0000x reference)
#include <cuda_runtime.h>
#include <math.h>

#define BB 16
#define TT 12
#define NN 300
#define DD 64
#define TW 10
#define NWIN (BB*TW)     // 160
#define NBT  (BB*TT)     // 192
#define K1C  6
#define K1R  50
#define K1_BLOCKS (NBT*K1C)   // 1152
#define SP 68                 // k1 smem row stride (pad)

__device__ float g_wfT[NBT*DD*NN];   // transposed wf per tile: [bt][i][n]
__device__ float g_Mt [NBT*DD*DD];   // per-tile M (atomic accumulated)
__device__ float g_kst[NBT*DD];      // per-tile ksum
__device__ float g_MW [NWIN*DD*DD];  // per-window M @ w1
__device__ float g_ksw[NWIN*DD];

typedef unsigned long long ull;

__device__ __forceinline__ ull pack2(float x) {
    ull r; asm("mov.b64 %0, {%1, %1};" : "=l"(r) : "f"(x)); return r;
}
__device__ __forceinline__ void ffma2(ull& d, ull a, ull b) {
    asm("fma.rn.f32x2 %0, %1, %2, %0;" : "+l"(d) : "l"(a), "l"(b));
}
__device__ __forceinline__ float2 unpk2(ull v) {
    float2 r; asm("mov.b64 {%0, %1}, %2;" : "=f"(r.x), "=f"(r.y) : "l"(v)); return r;
}

extern __shared__ float s_dyn[];

// ---------------------------------------------------------------------------
// k1: per (b,t, chunk of 50 rows): gate+normalize, write wf TRANSPOSED,
// rank-1 accumulate M into g_Mt (atomic) and ksum into g_kst.
// ---------------------------------------------------------------------------
__global__ void __launch_bounds__(128) k1(const float* __restrict__ feat,
                                          const float* __restrict__ weights) {
    float* se  = s_dyn;               // K1R*SP
    float* su  = se + K1R*SP;         // K1R*SP
    float* gws = su + K1R*SP;         // 64
    const int tid = threadIdx.x, bid = blockIdx.x;
    const int bt = bid / K1C, chunk = bid - bt*K1C;
    const int base = (bt*NN + chunk*K1R)*DD;

    if (tid < DD) gws[tid] = 1.f/(1.f + expf(-weights[tid]));
    {
        const float4* fsrc = (const float4*)(feat + base);
        for (int idx4 = tid; idx4 < K1R*16; idx4 += 128) {
            int r = idx4 >> 4, c4 = idx4 & 15;
            ((float4*)(se + r*SP))[c4] = fsrc[idx4];
        }
    }
    __syncthreads();

    {   // per-row inverse norm of gated vector; u = e*inv to smem
        const int wid = tid >> 5, lane = tid & 31;
        for (int r = wid; r < K1R; r += 4) {
            float e0 = se[r*SP + lane], e1 = se[r*SP + 32 + lane];
            float g0 = gws[lane]*e0, g1 = gws[lane+32]*e1;
            float ss = g0*g0 + g1*g1;
            #pragma unroll
            for (int o = 16; o; o >>= 1) ss += __shfl_xor_sync(0xffffffffu, ss, o);
            float inv = 1.f / fmaxf(sqrtf(ss), 1e-12f);
            su[r*SP + lane]      = e0*inv;
            su[r*SP + 32 + lane] = e1*inv;
        }
    }
    __syncthreads();

    // transposed wf write: wfT[bt][i][chunk*50 + r] = gws[i]*su[r][i]
    for (int idx = tid; idx < DD*K1R; idx += 128) {
        int i = idx / K1R, r = idx - i*K1R;
        g_wfT[(bt*DD + i)*NN + chunk*K1R + r] = gws[i]*su[r*SP + i];
    }

    // gram accumulation: 4(i) x 8(j) tile per thread, 16x8 thread grid
    const int tx = tid & 15, ty = tid >> 4;
    const int i0 = tx*4, j0 = ty*8;
    ull a00=0,a01=0,a02=0,a03=0;
    ull a10=0,a11=0,a12=0,a13=0;
    ull a20=0,a21=0,a22=0,a23=0;
    ull a30=0,a31=0,a32=0,a33=0;
    float ks0=0.f, ks1=0.f, ks2=0.f, ks3=0.f;

    #pragma unroll 2
    for (int r = 0; r < K1R; r++) {
        float4 uv = *(const float4*)(su + r*SP + i0);
        ulonglong2 eA = *(const ulonglong2*)(se + r*SP + j0);
        ulonglong2 eB = *(const ulonglong2*)(se + r*SP + j0 + 4);
        ull u0 = pack2(uv.x), u1 = pack2(uv.y), u2 = pack2(uv.z), u3 = pack2(uv.w);
        ffma2(a00,u0,eA.x); ffma2(a01,u0,eA.y); ffma2(a02,u0,eB.x); ffma2(a03,u0,eB.y);
        ffma2(a10,u1,eA.x); ffma2(a11,u1,eA.y); ffma2(a12,u1,eB.x); ffma2(a13,u1,eB.y);
        ffma2(a20,u2,eA.x); ffma2(a21,u2,eA.y); ffma2(a22,u2,eB.x); ffma2(a23,u2,eB.y);
        ffma2(a30,u3,eA.x); ffma2(a31,u3,eA.y); ffma2(a32,u3,eB.x); ffma2(a33,u3,eB.y);
        if (ty == 0) { ks0 += uv.x; ks1 += uv.y; ks2 += uv.z; ks3 += uv.w; }
    }

    float* Mt = g_Mt + bt*DD*DD;
    #pragma unroll
    for (int a = 0; a < 4; a++) {
        ull r0, r1, r2, r3;
        if (a == 0) { r0=a00; r1=a01; r2=a02; r3=a03; }
        else if (a == 1) { r0=a10; r1=a11; r2=a12; r3=a13; }
        else if (a == 2) { r0=a20; r1=a21; r2=a22; r3=a23; }
        else { r0=a30; r1=a31; r2=a32; r3=a33; }
        float gw = gws[i0 + a];
        float2 p0 = unpk2(r0), p1 = unpk2(r1), p2 = unpk2(r2), p3 = unpk2(r3);
        float* row = Mt + (i0+a)*DD + j0;
        atomicAdd(row+0, gw*p0.x); atomicAdd(row+1, gw*p0.y);
        atomicAdd(row+2, gw*p1.x); atomicAdd(row+3, gw*p1.y);
        atomicAdd(row+4, gw*p2.x); atomicAdd(row+5, gw*p2.y);
        atomicAdd(row+6, gw*p3.x); atomicAdd(row+7, gw*p3.y);
    }
    if (ty == 0) {
        atomicAdd(&g_kst[bt*DD + i0+0], gws[i0+0]*ks0);
        atomicAdd(&g_kst[bt*DD + i0+1], gws[i0+1]*ks1);
        atomicAdd(&g_kst[bt*DD + i0+2], gws[i0+2]*ks2);
        atomicAdd(&g_kst[bt*DD + i0+3], gws[i0+3]*ks3);
    }
}

// ---------------------------------------------------------------------------
// k1b: per window: M = sum of 3 tile-Ms; MW = M@w1; ksw = sum of tile ksums
// ---------------------------------------------------------------------------
__global__ void __launch_bounds__(256) k1b(const float* __restrict__ w1) {
    __shared__ float Ms [DD*DD];
    __shared__ float w1s[DD*DD];
    const int tid = threadIdx.x, w = blockIdx.x;
    const int b = w / TW, t2 = w - b*TW;
    const int bt0 = b*TT + t2;

    for (int idx = tid; idx < DD*DD; idx += 256) {
        Ms[idx] = g_Mt[(bt0+0)*DD*DD + idx]
                + g_Mt[(bt0+1)*DD*DD + idx]
                + g_Mt[(bt0+2)*DD*DD + idx];
        w1s[idx] = w1[idx];
    }
    if (tid < DD)
        g_ksw[w*DD + tid] = g_kst[(bt0+0)*DD + tid]
                          + g_kst[(bt0+1)*DD + tid]
                          + g_kst[(bt0+2)*DD + tid];
    __syncthreads();

    const int tx = tid & 15, ty = tid >> 4;
    const int i0 = ty*4, j0 = tx*4;
    float acc[4][4];
    #pragma unroll
    for (int a = 0; a < 4; a++)
        #pragma unroll
        for (int q = 0; q < 4; q++) acc[a][q] = 0.f;
    for (int k = 0; k < DD; k++) {
        float av[4], bv[4];
        #pragma unroll
        for (int a = 0; a < 4; a++) av[a] = Ms[(i0+a)*DD + k];
        #pragma unroll
        for (int q = 0; q < 4; q++) bv[q] = w1s[k*DD + j0+q];
        #pragma unroll
        for (int a = 0; a < 4; a++)
            #pragma unroll
            for (int q = 0; q < 4; q++) acc[a][q] += av[a]*bv[q];
    }
    float* MWo = g_MW + w*DD*DD;
    #pragma unroll
    for (int a = 0; a < 4; a++)
        #pragma unroll
        for (int q = 0; q < 4; q++) MWo[(i0+a)*DD + j0+q] = acc[a][q];
}

// ---------------------------------------------------------------------------
// k2: per (window, chunk of 100 rows). Thread = 4 rows x 8 cols. Q transposed
// + row-swizzled in smem; 2 FFMA2 GEMVs; residual + LayerNorm.
// swizzled addr for column c, row r: c*128 + (r ^ (((c>>3)&7)<<2))
// ---------------------------------------------------------------------------
__device__ __forceinline__ int swz(int c, int r) {
    return c*128 + (r ^ (((c >> 3) & 7) << 2));
}

__device__ __forceinline__ void gemv_8c4r(const float* __restrict__ sQt,
                                          const float* __restrict__ W,
                                          int r0, int c0, ull (&acc)[4][4]) {
    #pragma unroll
    for (int a = 0; a < 4; a++)
        #pragma unroll
        for (int q = 0; q < 4; q++) acc[a][q] = 0ull;
    #pragma unroll 4
    for (int i = 0; i < DD; i++) {
        const float4 q4 = *(const float4*)(sQt + swz(i, r0));
        ull q0 = pack2(q4.x), q1 = pack2(q4.y), q2 = pack2(q4.z), q3 = pack2(q4.w);
        ulonglong2 wA = *(const ulonglong2*)(W + i*DD + c0);
        ulonglong2 wB = *(const ulonglong2*)(W + i*DD + c0 + 4);
        ffma2(acc[0][0],q0,wA.x); ffma2(acc[0][1],q0,wA.y); ffma2(acc[0][2],q0,wB.x); ffma2(acc[0][3],q0,wB.y);
        ffma2(acc[1][0],q1,wA.x); ffma2(acc[1][1],q1,wA.y); ffma2(acc[1][2],q1,wB.x); ffma2(acc[1][3],q1,wB.y);
        ffma2(acc[2][0],q2,wA.x); ffma2(acc[2][1],q2,wA.y); ffma2(acc[2][2],q2,wB.x); ffma2(acc[2][3],q2,wB.y);
        ffma2(acc[3][0],q3,wA.x); ffma2(acc[3][1],q3,wA.y); ffma2(acc[3][2],q3,wB.x); ffma2(acc[3][3],q3,wB.y);
    }
}

__global__ void __launch_bounds__(128) k2(const float* __restrict__ feat,
                                          const float* __restrict__ b1,
                                          const float* __restrict__ w2,
                                          const float* __restrict__ b2,
                                          const float* __restrict__ gamma,
                                          const float* __restrict__ beta,
                                          float* __restrict__ out) {
    float* sMW = s_dyn;           // 4096
    float* sW2 = sMW + 4096;      // 4096
    float* sQt = sW2 + 4096;      // 64*128 = 8192 (Q then reused for h)
    float* sKs = sQt + 8192;      // 64
    float* sDi = sKs + 64;        // 128

    const int tid = threadIdx.x, bid = blockIdx.x;
    const int w = bid / 3, chunk = bid - w*3;
    const int b = w / TW, t2 = w - b*TW;
    const int bt = b*TT + t2 + 2;
    const int rowbase = (bt*NN + chunk*100)*DD;

    {
        float4* dMW = (float4*)sMW; const float4* gMW = (const float4*)(g_MW + w*4096);
        float4* dW2 = (float4*)sW2; const float4* gW2 = (const float4*)w2;
        for (int idx = tid; idx < 1024; idx += 128) { dMW[idx] = gMW[idx]; dW2[idx] = gW2[idx]; }
        const float* gq = g_wfT + (bt*DD)*NN + chunk*100;
        for (int idx4 = tid; idx4 < DD*32; idx4 += 128) {
            int i = idx4 >> 5, rr4 = idx4 & 31, r0 = rr4*4;
            float4 v = make_float4(0.f,0.f,0.f,0.f);
            if (rr4 < 25) v = *(const float4*)(gq + i*NN + r0);
            *(float4*)(sQt + swz(i, r0)) = v;
        }
        if (tid < DD) sKs[tid] = g_ksw[w*DD + tid];
    }
    __syncthreads();

    // deg pre-pass: one thread per row
    if (tid < 100) {
        float dg = 0.f;
        #pragma unroll 8
        for (int i = 0; i < DD; i++) dg += sQt[swz(i, tid)] * sKs[i];
        sDi[tid] = (dg == 0.f) ? 0.f : 1.f/dg;
    } else {
        sDi[tid] = 0.f;
    }
    __syncthreads();

    const int wid = tid >> 5, lane = tid & 31;
    const int rg = lane >> 3, cg = lane & 7;
    const int c0 = cg*8;
    float b1g[8];
    {
        float4 bA = *(const float4*)(b1 + c0), bB = *(const float4*)(b1 + c0 + 4);
        b1g[0]=bA.x; b1g[1]=bA.y; b1g[2]=bA.z; b1g[3]=bA.w;
        b1g[4]=bB.x; b1g[5]=bB.y; b1g[6]=bB.z; b1g[7]=bB.w;
    }
    const unsigned omask = 0xFFu << (lane & 24);
    ull acc[4][4];

    #pragma unroll 1
    for (int pass = 0; pass < 2; pass++) {
        const int r0 = pass*64 + wid*16 + rg*4;
        float4 di4 = *(const float4*)(sDi + r0);
        const float* dip = (const float*)&di4;

        // GEMV1: S = q @ MW ; h = relu(S*dinv + b1) -> write back transposed
        gemv_8c4r(sQt, sMW, r0, c0, acc);
        __syncwarp();
        #pragma unroll
        for (int rr = 0; rr < 4; rr++) {
            float di = dip[rr];
            #pragma unroll
            for (int cp = 0; cp < 4; cp++) {
                float2 p = unpk2(acc[rr][cp]);
                int c = c0 + cp*2;
                sQt[swz(c,   r0+rr)] = fmaxf(p.x*di + b1g[cp*2],   0.f);
                sQt[swz(c+1, r0+rr)] = fmaxf(p.y*di + b1g[cp*2+1], 0.f);
            }
        }
        __syncwarp();

        // GEMV2: v = h @ W2
        gemv_8c4r(sQt, sW2, r0, c0, acc);

        // epilogue: + b2 + feat, LayerNorm, store
        #pragma unroll
        for (int rr = 0; rr < 4; rr++) {
            int r = r0 + rr;
            if (r < 100) {
                float v[8];
                #pragma unroll
                for (int cp = 0; cp < 4; cp++) {
                    float2 p = unpk2(acc[rr][cp]);
                    v[cp*2] = p.x; v[cp*2+1] = p.y;
                }
                float4 fA = *(const float4*)(feat + rowbase + r*DD + c0);
                float4 fB = *(const float4*)(feat + rowbase + r*DD + c0 + 4);
                float4 bA = *(const float4*)(b2 + c0);
                float4 bB = *(const float4*)(b2 + c0 + 4);
                v[0]+=fA.x+bA.x; v[1]+=fA.y+bA.y; v[2]+=fA.z+bA.z; v[3]+=fA.w+bA.w;
                v[4]+=fB.x+bB.x; v[5]+=fB.y+bB.y; v[6]+=fB.z+bB.z; v[7]+=fB.w+bB.w;
                float s = v[0]+v[1]+v[2]+v[3]+v[4]+v[5]+v[6]+v[7];
                s += __shfl_xor_sync(omask, s, 1);
                s += __shfl_xor_sync(omask, s, 2);
                s += __shfl_xor_sync(omask, s, 4);
                float mu = s * (1.f/DD);
                float ss = 0.f;
                #pragma unroll
                for (int j = 0; j < 8; j++) { v[j] -= mu; ss += v[j]*v[j]; }
                ss += __shfl_xor_sync(omask, ss, 1);
                ss += __shfl_xor_sync(omask, ss, 2);
                ss += __shfl_xor_sync(omask, ss, 4);
                float rs = rsqrtf(ss * (1.f/DD) + 1e-5f);
                float4 gA = *(const float4*)(gamma + c0);
                float4 gB = *(const float4*)(gamma + c0 + 4);
                float4 eA = *(const float4*)(beta + c0);
                float4 eB = *(const float4*)(beta + c0 + 4);
                float4 oA, oB;
                oA.x = v[0]*rs*gA.x + eA.x; oA.y = v[1]*rs*gA.y + eA.y;
                oA.z = v[2]*rs*gA.z + eA.z; oA.w = v[3]*rs*gA.w + eA.w;
                oB.x = v[4]*rs*gB.x + eB.x; oB.y = v[5]*rs*gB.y + eB.y;
                oB.z = v[6]*rs*gB.z + eB.z; oB.w = v[7]*rs*gB.w + eB.w;
                float* op = out + (w*NN + chunk*100 + r)*DD + c0;
                *(float4*)op = oA;
                *(float4*)(op + 4) = oB;
            }
        }
    }
}

extern "C" void kernel_launch(void* const* d_in, const int* in_sizes, int n_in,
                              void* d_out, int out_size) {
    const float* feat    = (const float*)d_in[0];
    const float* weights = (const float*)d_in[1];
    const float* w1      = (const float*)d_in[2];
    const float* b1      = (const float*)d_in[3];
    const float* w2      = (const float*)d_in[4];
    const float* b2      = (const float*)d_in[5];
    const float* gamma   = (const float*)d_in[6];
    const float* beta    = (const float*)d_in[7];
    float* out = (float*)d_out;

    const size_t smem1 = (2*K1R*SP + DD) * sizeof(float);
    const size_t smem2 = (4096 + 4096 + 8192 + 64 + 128) * sizeof(float);

    float* pMt = nullptr;
    float* pKst = nullptr;
    cudaGetSymbolAddress((void**)&pMt, g_Mt);
    cudaGetSymbolAddress((void**)&pKst, g_kst);
    cudaFuncSetAttribute(k1, cudaFuncAttributeMaxDynamicSharedMemorySize, (int)smem1);
    cudaFuncSetAttribute(k2, cudaFuncAttributeMaxDynamicSharedMemorySize, (int)smem2);

    cudaMemsetAsync(pMt, 0, NBT*DD*DD*sizeof(float));
    cudaMemsetAsync(pKst, 0, NBT*DD*sizeof(float));
    k1 <<<K1_BLOCKS, 128, smem1>>>(feat, weights);
    k1b<<<NWIN, 256>>>(w1);
    k2 <<<NWIN*3, 128, smem2>>>(feat, b1, w2, b2, gamma, beta, out);
}

// round 10
// speedup vs baseline: 1.7677x; 1.7677x over previous
#include <cuda_runtime.h>
#include <math.h>

#define BB 16
#define TT 12
#define NN 300
#define DD 64
#define TW 10
#define NWIN (BB*TW)     // 160
#define NBT  (BB*TT)     // 192
#define K1C  3
#define K1R  100
#define K1_BLOCKS (NBT*K1C)   // 576
#define SP 68                 // smem row stride (pad)

__device__ float g_wf [NBT*NN*DD];   // gated+normalized rows (row-major)
__device__ float g_Mtp[K1_BLOCKS*DD*DD];
__device__ float g_ksp[K1_BLOCKS*DD];
__device__ float g_MW [NWIN*DD*DD];  // per-window M @ w1
__device__ float g_ksw[NWIN*DD];

typedef unsigned long long ull;

__device__ __forceinline__ ull pack2(float x) {
    ull r; asm("mov.b64 %0, {%1, %1};" : "=l"(r) : "f"(x)); return r;
}
__device__ __forceinline__ void ffma2(ull& d, ull a, ull b) {
    asm("fma.rn.f32x2 %0, %1, %2, %0;" : "+l"(d) : "l"(a), "l"(b));
}
__device__ __forceinline__ float2 unpk2(ull v) {
    float2 r; asm("mov.b64 {%0, %1}, %2;" : "=f"(r.x), "=f"(r.y) : "l"(v)); return r;
}

extern __shared__ float s_dyn[];

// ---------------------------------------------------------------------------
// k1: per (b,t, chunk of 100 rows): gate + L2-normalize (write g_wf),
// store v = e*sqrt(inv) in place, accumulate G = sum v v^T; M = diag(gws)*G.
// ---------------------------------------------------------------------------
__global__ void __launch_bounds__(128) k1(const float* __restrict__ feat,
                                          const float* __restrict__ weights) {
    float* sv   = s_dyn;              // K1R*SP
    float* snrm = sv + K1R*SP;        // K1R   (stores s = sqrt(inv))
    float* gws  = snrm + K1R;         // 64
    const int tid = threadIdx.x, bid = blockIdx.x;
    const int bt = bid / K1C, chunk = bid - bt*K1C;
    const int base = (bt*NN + chunk*K1R)*DD;

    if (tid < DD) gws[tid] = 1.f/(1.f + expf(-weights[tid]));
    {
        const float4* fsrc = (const float4*)(feat + base);
        for (int idx4 = tid; idx4 < K1R*16; idx4 += 128) {
            int r = idx4 >> 4, c4 = idx4 & 15;
            ((float4*)(sv + r*SP))[c4] = fsrc[idx4];
        }
    }
    __syncthreads();

    {   // norm phase: each row handled by one warp
        const int wid = tid >> 5, lane = tid & 31;
        for (int r = wid; r < K1R; r += 4) {
            float e0 = sv[r*SP + lane], e1 = sv[r*SP + 32 + lane];
            float g0 = gws[lane]*e0, g1 = gws[lane+32]*e1;
            float ss = g0*g0 + g1*g1;
            #pragma unroll
            for (int o = 16; o; o >>= 1) ss += __shfl_xor_sync(0xffffffffu, ss, o);
            float s = rsqrtf(fmaxf(sqrtf(ss), 1e-12f));   // s = sqrt(1/max(nrm,eps))
            float v0 = e0*s, v1 = e1*s;
            g_wf[base + r*DD + lane]      = gws[lane]*v0*s;     // = g0*inv
            g_wf[base + r*DD + 32 + lane] = gws[lane+32]*v1*s;
            sv[r*SP + lane]      = v0;
            sv[r*SP + 32 + lane] = v1;
            if (lane == 0) snrm[r] = s;
        }
    }
    __syncthreads();

    // gram: thread (tx,ty) covers G[i0..i0+3][j0..j0+7]
    const int tx = tid & 15, ty = tid >> 4;
    const int i0 = tx*4, j0 = ty*8;
    ull acc[4][4];
    #pragma unroll
    for (int a = 0; a < 4; a++)
        #pragma unroll
        for (int p = 0; p < 4; p++) acc[a][p] = 0ull;
    float ks0=0.f, ks1=0.f, ks2=0.f, ks3=0.f;

    #pragma unroll 2
    for (int r = 0; r < K1R; r++) {
        float4 vi = *(const float4*)(sv + r*SP + i0);
        ulonglong2 vA = *(const ulonglong2*)(sv + r*SP + j0);
        ulonglong2 vB = *(const ulonglong2*)(sv + r*SP + j0 + 4);
        ull u0 = pack2(vi.x), u1 = pack2(vi.y), u2 = pack2(vi.z), u3 = pack2(vi.w);
        ffma2(acc[0][0],u0,vA.x); ffma2(acc[0][1],u0,vA.y); ffma2(acc[0][2],u0,vB.x); ffma2(acc[0][3],u0,vB.y);
        ffma2(acc[1][0],u1,vA.x); ffma2(acc[1][1],u1,vA.y); ffma2(acc[1][2],u1,vB.x); ffma2(acc[1][3],u1,vB.y);
        ffma2(acc[2][0],u2,vA.x); ffma2(acc[2][1],u2,vA.y); ffma2(acc[2][2],u2,vB.x); ffma2(acc[2][3],u2,vB.y);
        ffma2(acc[3][0],u3,vA.x); ffma2(acc[3][1],u3,vA.y); ffma2(acc[3][2],u3,vB.x); ffma2(acc[3][3],u3,vB.y);
        if (ty == 0) {
            float s = snrm[r];
            ks0 += s*vi.x; ks1 += s*vi.y; ks2 += s*vi.z; ks3 += s*vi.w;
        }
    }

    float* Mout = g_Mtp + bid*DD*DD;
    #pragma unroll
    for (int a = 0; a < 4; a++) {
        float gw = gws[i0 + a];
        float2 p0 = unpk2(acc[a][0]), p1 = unpk2(acc[a][1]);
        float2 p2 = unpk2(acc[a][2]), p3 = unpk2(acc[a][3]);
        *(float4*)(Mout + (i0+a)*DD + j0)     = make_float4(gw*p0.x, gw*p0.y, gw*p1.x, gw*p1.y);
        *(float4*)(Mout + (i0+a)*DD + j0 + 4) = make_float4(gw*p2.x, gw*p2.y, gw*p3.x, gw*p3.y);
    }
    if (ty == 0) {
        float* kso = g_ksp + bid*DD + i0;
        kso[0] = gws[i0+0]*ks0; kso[1] = gws[i0+1]*ks1;
        kso[2] = gws[i0+2]*ks2; kso[3] = gws[i0+3]*ks3;
    }
}

// ---------------------------------------------------------------------------
// k1b: per window: M = sum of 9 partials; MW = M@w1; ksw = sum of ksum partials
// ---------------------------------------------------------------------------
__global__ void __launch_bounds__(256) k1b(const float* __restrict__ w1) {
    __shared__ float Ms [DD*DD];
    __shared__ float w1s[DD*DD];
    const int tid = threadIdx.x, w = blockIdx.x;
    const int b = w / TW, t2 = w - b*TW;
    const int bt0 = b*TT + t2;

    for (int idx = tid; idx < DD*DD; idx += 256) {
        float s = 0.f;
        #pragma unroll
        for (int dt = 0; dt < 3; dt++)
            #pragma unroll
            for (int c = 0; c < K1C; c++)
                s += g_Mtp[((bt0+dt)*K1C + c)*DD*DD + idx];
        Ms[idx] = s;
        w1s[idx] = w1[idx];
    }
    if (tid < DD) {
        float s = 0.f;
        #pragma unroll
        for (int dt = 0; dt < 3; dt++)
            #pragma unroll
            for (int c = 0; c < K1C; c++)
                s += g_ksp[((bt0+dt)*K1C + c)*DD + tid];
        g_ksw[w*DD + tid] = s;
    }
    __syncthreads();

    const int tx = tid & 15, ty = tid >> 4;
    const int i0 = ty*4, j0 = tx*4;
    float acc[4][4];
    #pragma unroll
    for (int a = 0; a < 4; a++)
        #pragma unroll
        for (int q = 0; q < 4; q++) acc[a][q] = 0.f;
    for (int k = 0; k < DD; k++) {
        float av[4], bv[4];
        #pragma unroll
        for (int a = 0; a < 4; a++) av[a] = Ms[(i0+a)*DD + k];
        #pragma unroll
        for (int q = 0; q < 4; q++) bv[q] = w1s[k*DD + j0+q];
        #pragma unroll
        for (int a = 0; a < 4; a++)
            #pragma unroll
            for (int q = 0; q < 4; q++) acc[a][q] += av[a]*bv[q];
    }
    float* MWo = g_MW + w*DD*DD;
    #pragma unroll
    for (int a = 0; a < 4; a++)
        #pragma unroll
        for (int q = 0; q < 4; q++) MWo[(i0+a)*DD + j0+q] = acc[a][q];
}

// ---------------------------------------------------------------------------
// k2: block = (window, chunk of up to 128 rows) x 64 cols; thread = 8r x 8c.
// Row-major A in smem (stride 68, col-swizzled by row-group for bank spread).
// ---------------------------------------------------------------------------
__device__ __forceinline__ void gemv8x8(const float* __restrict__ sArow, int sw,
                                        const float* __restrict__ W, int c0,
                                        ull (&acc)[8][4]) {
    #pragma unroll
    for (int i = 0; i < 8; i++)
        #pragma unroll
        for (int p = 0; p < 4; p++) acc[i][p] = 0ull;
    #pragma unroll 2
    for (int k4 = 0; k4 < 16; k4++) {
        const int k = k4*4;
        float4 av[8];
        #pragma unroll
        for (int i = 0; i < 8; i++)
            av[i] = *(const float4*)(sArow + i*SP + (k ^ sw));
        #pragma unroll
        for (int kk = 0; kk < 4; kk++) {
            const float* wrow = W + (k+kk)*DD + c0;
            ulonglong2 wA = *(const ulonglong2*)(wrow);
            ulonglong2 wB = *(const ulonglong2*)(wrow + 4);
            #pragma unroll
            for (int i = 0; i < 8; i++) {
                float a = (kk==0) ? av[i].x : (kk==1) ? av[i].y : (kk==2) ? av[i].z : av[i].w;
                ull p = pack2(a);
                ffma2(acc[i][0], p, wA.x); ffma2(acc[i][1], p, wA.y);
                ffma2(acc[i][2], p, wB.x); ffma2(acc[i][3], p, wB.y);
            }
        }
    }
}

__global__ void __launch_bounds__(128) k2(const float* __restrict__ feat,
                                          const float* __restrict__ b1,
                                          const float* __restrict__ w2,
                                          const float* __restrict__ b2,
                                          const float* __restrict__ gamma,
                                          const float* __restrict__ beta,
                                          float* __restrict__ out) {
    float* sA  = s_dyn;            // 128*SP
    float* sMW = sA + 128*SP;      // 4096
    float* sW2 = sMW + 4096;       // 4096
    float* sDi = sW2 + 4096;       // 128
    float* sKs = sDi + 128;        // 64

    const int tid = threadIdx.x, bid = blockIdx.x;
    const int w = bid / 3, chunk = bid - w*3;
    const int b = w / TW, t2 = w - b*TW;
    const int bt = b*TT + t2 + 2;
    const int row0 = chunk*128;
    const int rows = (chunk < 2) ? 128 : (NN - 256);   // 128,128,44
    const int rowbase = (bt*NN + row0)*DD;

    {
        float4* dMW = (float4*)sMW; const float4* gMW = (const float4*)(g_MW + w*4096);
        float4* dW2 = (float4*)sW2; const float4* gW2 = (const float4*)w2;
        for (int idx = tid; idx < 1024; idx += 128) { dMW[idx] = gMW[idx]; dW2[idx] = gW2[idx]; }
        const float4* gq = (const float4*)(g_wf + rowbase);
        for (int idx4 = tid; idx4 < 128*16; idx4 += 128) {
            int r = idx4 >> 4, c = (idx4 & 15)*4;
            float4 v = make_float4(0.f,0.f,0.f,0.f);
            if (r < rows) v = gq[r*16 + (c>>2)];
            int sw = ((r >> 3) & 3) << 3;
            *(float4*)(sA + r*SP + (c ^ sw)) = v;
        }
        if (tid < DD) sKs[tid] = g_ksw[w*DD + tid];
    }
    __syncthreads();

    {   // deg pre-pass: one thread per row
        int r = tid, sw = ((r >> 3) & 3) << 3;
        float dg = 0.f;
        #pragma unroll
        for (int k4 = 0; k4 < 16; k4++) {
            float4 q4 = *(const float4*)(sA + r*SP + ((k4*4) ^ sw));
            float4 s4 = *(const float4*)(sKs + k4*4);
            dg += q4.x*s4.x + q4.y*s4.y + q4.z*s4.z + q4.w*s4.w;
        }
        sDi[r] = (dg == 0.f) ? 0.f : 1.f/dg;
    }
    __syncthreads();

    const int rg = tid >> 3, cg = tid & 7;
    const int r0 = rg*8, c0 = cg*8;
    const int sw = (rg & 3) << 3;
    const float* sArow = sA + r0*SP;
    ull acc[8][4];

    // GEMV1: S = q @ MW ; h = relu(S*dinv + b1), written back in place
    gemv8x8(sArow, sw, sMW, c0, acc);
    float di[8];
    {
        float4 dA = *(const float4*)(sDi + r0);
        float4 dB = *(const float4*)(sDi + r0 + 4);
        di[0]=dA.x; di[1]=dA.y; di[2]=dA.z; di[3]=dA.w;
        di[4]=dB.x; di[5]=dB.y; di[6]=dB.z; di[7]=dB.w;
    }
    float4 b1A = *(const float4*)(b1 + c0), b1B = *(const float4*)(b1 + c0 + 4);
    __syncwarp();
    #pragma unroll
    for (int i = 0; i < 8; i++) {
        float2 p0 = unpk2(acc[i][0]), p1 = unpk2(acc[i][1]);
        float2 p2 = unpk2(acc[i][2]), p3 = unpk2(acc[i][3]);
        float4 h0, h1;
        h0.x = fmaxf(p0.x*di[i] + b1A.x, 0.f); h0.y = fmaxf(p0.y*di[i] + b1A.y, 0.f);
        h0.z = fmaxf(p1.x*di[i] + b1A.z, 0.f); h0.w = fmaxf(p1.y*di[i] + b1A.w, 0.f);
        h1.x = fmaxf(p2.x*di[i] + b1B.x, 0.f); h1.y = fmaxf(p2.y*di[i] + b1B.y, 0.f);
        h1.z = fmaxf(p3.x*di[i] + b1B.z, 0.f); h1.w = fmaxf(p3.y*di[i] + b1B.w, 0.f);
        *(float4*)(sArow + i*SP + (c0 ^ sw))       = h0;
        *(float4*)(sArow + i*SP + ((c0+4) ^ sw))   = h1;
    }
    __syncwarp();

    // GEMV2: v = h @ W2
    gemv8x8(sArow, sw, sW2, c0, acc);

    // epilogue: + b2 + feat, LayerNorm over 64 (8 cols in-thread + 8-lane shfl)
    float4 b2A = *(const float4*)(b2 + c0),   b2B = *(const float4*)(b2 + c0 + 4);
    float4 gA  = *(const float4*)(gamma + c0), gB = *(const float4*)(gamma + c0 + 4);
    float4 eA  = *(const float4*)(beta + c0),  eB = *(const float4*)(beta + c0 + 4);
    #pragma unroll
    for (int i = 0; i < 8; i++) {
        int r = r0 + i;
        float v[8];
        {
            float2 p0 = unpk2(acc[i][0]), p1 = unpk2(acc[i][1]);
            float2 p2 = unpk2(acc[i][2]), p3 = unpk2(acc[i][3]);
            v[0]=p0.x; v[1]=p0.y; v[2]=p1.x; v[3]=p1.y;
            v[4]=p2.x; v[5]=p2.y; v[6]=p3.x; v[7]=p3.y;
        }
        if (r < rows) {
            const float* fp = feat + rowbase + r*DD + c0;
            float4 fA = *(const float4*)(fp), fB = *(const float4*)(fp + 4);
            v[0]+=b2A.x+fA.x; v[1]+=b2A.y+fA.y; v[2]+=b2A.z+fA.z; v[3]+=b2A.w+fA.w;
            v[4]+=b2B.x+fB.x; v[5]+=b2B.y+fB.y; v[6]+=b2B.z+fB.z; v[7]+=b2B.w+fB.w;
        }
        float s = v[0]+v[1]+v[2]+v[3]+v[4]+v[5]+v[6]+v[7];
        s += __shfl_xor_sync(0xffffffffu, s, 1);
        s += __shfl_xor_sync(0xffffffffu, s, 2);
        s += __shfl_xor_sync(0xffffffffu, s, 4);
        float mu = s * (1.f/DD);
        float ss = 0.f;
        #pragma unroll
        for (int j = 0; j < 8; j++) { v[j] -= mu; ss += v[j]*v[j]; }
        ss += __shfl_xor_sync(0xffffffffu, ss, 1);
        ss += __shfl_xor_sync(0xffffffffu, ss, 2);
        ss += __shfl_xor_sync(0xffffffffu, ss, 4);
        float rs = rsqrtf(ss * (1.f/DD) + 1e-5f);
        if (r < rows) {
            float4 oA, oB;
            oA.x = v[0]*rs*gA.x + eA.x; oA.y = v[1]*rs*gA.y + eA.y;
            oA.z = v[2]*rs*gA.z + eA.z; oA.w = v[3]*rs*gA.w + eA.w;
            oB.x = v[4]*rs*gB.x + eB.x; oB.y = v[5]*rs*gB.y + eB.y;
            oB.z = v[6]*rs*gB.z + eB.z; oB.w = v[7]*rs*gB.w + eB.w;
            float* op = out + (w*NN + row0 + r)*DD + c0;
            *(float4*)op = oA;
            *(float4*)(op + 4) = oB;
        }
    }
}

extern "C" void kernel_launch(void* const* d_in, const int* in_sizes, int n_in,
                              void* d_out, int out_size) {
    const float* feat    = (const float*)d_in[0];
    const float* weights = (const float*)d_in[1];
    const float* w1      = (const float*)d_in[2];
    const float* b1      = (const float*)d_in[3];
    const float* w2      = (const float*)d_in[4];
    const float* b2      = (const float*)d_in[5];
    const float* gamma   = (const float*)d_in[6];
    const float* beta    = (const float*)d_in[7];
    float* out = (float*)d_out;

    const size_t smem1 = (K1R*SP + K1R + DD) * sizeof(float);           // ~27.9KB
    const size_t smem2 = (128*SP + 4096 + 4096 + 128 + DD) * sizeof(float); // ~68.3KB

    cudaFuncSetAttribute(k1, cudaFuncAttributeMaxDynamicSharedMemorySize, (int)smem1);
    cudaFuncSetAttribute(k2, cudaFuncAttributeMaxDynamicSharedMemorySize, (int)smem2);

    k1 <<<K1_BLOCKS, 128, smem1>>>(feat, weights);
    k1b<<<NWIN, 256>>>(w1);
    k2 <<<NWIN*3, 128, smem2>>>(feat, b1, w2, b2, gamma, beta, out);
}